// round 1
// baseline (speedup 1.0000x reference)
#include <cuda_runtime.h>
#include <cuda_bf16.h>
#include <math.h>

// Problem constants
#define BATCH 1024
#define TT    256
#define II    153
#define HH    128
#define G3    384   // 3*H
#define MTOT  (BATCH*TT)   // 262144

// ---------------------------------------------------------------------------
// Scratch (device globals — no runtime allocation allowed)
// ---------------------------------------------------------------------------
__device__ float g_gi[(size_t)MTOT * G3];    // ~403 MB: gi0, later reused for gi1
__device__ float g_seq[(size_t)MTOT * HH];   // ~134 MB: layer-0 output sequence
__device__ float g_hlast[BATCH * HH];        // layer-1 final hidden state

// ---------------------------------------------------------------------------
// Kernel 1/3: C[M,N] = A[M,K] @ W[N,K]^T + bias[N]
// Block tile 64x64, BK=16, 256 threads, 4x4 register tile per thread.
// ---------------------------------------------------------------------------
#define BM 64
#define BN 64
#define BK 16

__global__ __launch_bounds__(256)
void gemm_bias(const float* __restrict__ A, const float* __restrict__ W,
               const float* __restrict__ bias, float* __restrict__ C,
               int M, int N, int K)
{
    __shared__ float As[BK][BM + 4];
    __shared__ float Bs[BK][BN + 4];

    const int tid = threadIdx.x;
    const int tn = tid & 15;        // 0..15
    const int tm = tid >> 4;        // 0..15
    const int m0 = blockIdx.x * BM;
    const int n0 = blockIdx.y * BN;

    float acc[4][4];
#pragma unroll
    for (int i = 0; i < 4; i++)
#pragma unroll
        for (int j = 0; j < 4; j++) acc[i][j] = 0.f;

    for (int k0 = 0; k0 < K; k0 += BK) {
        // Load A tile (BM x BK) and W tile (BN x BK); both are K-major rows.
#pragma unroll
        for (int i = tid; i < BM * BK; i += 256) {
            int mm = i >> 4;            // /BK
            int kk = i & 15;            // %BK
            int k  = k0 + kk;
            As[kk][mm] = (k < K) ? A[(size_t)(m0 + mm) * K + k] : 0.f;
        }
#pragma unroll
        for (int i = tid; i < BN * BK; i += 256) {
            int nn = i >> 4;
            int kk = i & 15;
            int k  = k0 + kk;
            Bs[kk][nn] = (k < K) ? W[(size_t)(n0 + nn) * K + k] : 0.f;
        }
        __syncthreads();

#pragma unroll
        for (int kk = 0; kk < BK; kk++) {
            float a[4], b[4];
#pragma unroll
            for (int i = 0; i < 4; i++) a[i] = As[kk][tm * 4 + i];
#pragma unroll
            for (int j = 0; j < 4; j++) b[j] = Bs[kk][tn * 4 + j];
#pragma unroll
            for (int i = 0; i < 4; i++)
#pragma unroll
                for (int j = 0; j < 4; j++) acc[i][j] += a[i] * b[j];
        }
        __syncthreads();
    }

#pragma unroll
    for (int i = 0; i < 4; i++) {
        int m = m0 + tm * 4 + i;
#pragma unroll
        for (int j = 0; j < 4; j++) {
            int n = n0 + tn * 4 + j;
            C[(size_t)m * N + n] = acc[i][j] + bias[n];
        }
    }
}

// ---------------------------------------------------------------------------
// Kernel 2/4: GRU recurrence over time, batch-parallel.
// One CTA = NB batch rows, 384 threads (thread g owns gate index g).
// W_hh kept transposed in smem: Wt[k][g] -> conflict-free lane-consecutive reads.
// h kept in smem (broadcast reads in the k-loop).
// gates: g in [0,128) = r, [128,256) = z, [256,384) = n (warp-uniform split).
// ---------------------------------------------------------------------------
#define NB 8
#define GRU_SMEM ((128*G3 + 3*NB*HH) * sizeof(float))   // 208896 bytes

__global__ __launch_bounds__(G3)
void gru_layer(const float* __restrict__ gi,     // [B*T, 384], m = b*T + t
               const float* __restrict__ W_hh,   // [384, 128]
               const float* __restrict__ b_hh,   // [384]
               float* __restrict__ seq_out,      // [B*T, 128] or unused
               float* __restrict__ hlast_out,    // [B, 128] or unused
               int write_seq)
{
    extern __shared__ float sm[];
    float* Wt = sm;                      // [128][384]
    float* h  = sm + 128 * G3;           // [NB][128]
    float* rb = h  + NB * HH;            // [NB][128]
    float* zb = rb + NB * HH;            // [NB][128]

    const int g  = threadIdx.x;          // 0..383
    const int b0 = blockIdx.x * NB;
    const int j  = g & 127;
    const int gtype = g >> 7;            // 0=r, 1=z, 2=n

    // Load W_hh transposed into smem
#pragma unroll 4
    for (int k = 0; k < HH; k++)
        Wt[k * G3 + g] = W_hh[g * HH + k];
    // Zero h
    for (int i = g; i < NB * HH; i += G3) h[i] = 0.f;

    const float bh = b_hh[g];
    __syncthreads();

    for (int t = 0; t < TT; t++) {
        // Prefetch gi for this step (independent of h -> latency hidden by k-loop)
        float giv[NB];
#pragma unroll
        for (int b = 0; b < NB; b++)
            giv[b] = gi[((size_t)((b0 + b) * TT + t)) * G3 + g];

        float acc[NB];
#pragma unroll
        for (int b = 0; b < NB; b++) acc[b] = bh;

#pragma unroll 4
        for (int k = 0; k < HH; k++) {
            float w = Wt[k * G3 + g];
#pragma unroll
            for (int b = 0; b < NB; b++)
                acc[b] += w * h[b * HH + k];
        }

        if (gtype == 0) {
#pragma unroll
            for (int b = 0; b < NB; b++)
                rb[b * HH + j] = 1.f / (1.f + expf(-(giv[b] + acc[b])));
        } else if (gtype == 1) {
#pragma unroll
            for (int b = 0; b < NB; b++)
                zb[b * HH + j] = 1.f / (1.f + expf(-(giv[b] + acc[b])));
        }
        __syncthreads();

        if (gtype == 2) {
#pragma unroll
            for (int b = 0; b < NB; b++) {
                float r  = rb[b * HH + j];
                float z  = zb[b * HH + j];
                float n  = tanhf(giv[b] + r * acc[b]);   // gi_n and gh_n kept separate
                float hn = (1.f - z) * n + z * h[b * HH + j];
                h[b * HH + j] = hn;
                if (write_seq)
                    seq_out[((size_t)((b0 + b) * TT + t)) * HH + j] = hn;
            }
        }
        __syncthreads();
    }

    if (!write_seq && gtype == 2) {
#pragma unroll
        for (int b = 0; b < NB; b++)
            hlast_out[(b0 + b) * HH + j] = h[b * HH + j];
    }
}

// ---------------------------------------------------------------------------
// Kernel 5: head — Linear(128,64) -> ReLU -> Linear(64,1) -> Sigmoid
// One block per batch row, 64 threads.
// ---------------------------------------------------------------------------
__global__ __launch_bounds__(64)
void head_kernel(const float* __restrict__ hlast, const float* __restrict__ W1,
                 const float* __restrict__ b1, const float* __restrict__ W2,
                 const float* __restrict__ b2, float* __restrict__ out)
{
    __shared__ float hs[HH];
    __shared__ float partial[2];
    const int b = blockIdx.x, tid = threadIdx.x;

    hs[tid]      = hlast[b * HH + tid];
    hs[tid + 64] = hlast[b * HH + 64 + tid];
    __syncthreads();

    float acc = b1[tid];
#pragma unroll 4
    for (int k = 0; k < HH; k++)
        acc += hs[k] * W1[tid * HH + k];
    float v = fmaxf(acc, 0.f) * W2[tid];

#pragma unroll
    for (int o = 16; o > 0; o >>= 1)
        v += __shfl_down_sync(0xffffffffu, v, o);
    if ((tid & 31) == 0) partial[tid >> 5] = v;
    __syncthreads();
    if (tid == 0)
        out[b] = 1.f / (1.f + expf(-(partial[0] + partial[1] + b2[0])));
}

// ---------------------------------------------------------------------------
// Launch: proj0 -> rec0 -> proj1 (reuses g_gi) -> rec1 -> head
// ---------------------------------------------------------------------------
extern "C" void kernel_launch(void* const* d_in, const int* in_sizes, int n_in,
                              void* d_out, int out_size)
{
    (void)in_sizes; (void)n_in; (void)out_size;
    const float* x     = (const float*)d_in[0];
    const float* W_ih0 = (const float*)d_in[1];
    const float* W_hh0 = (const float*)d_in[2];
    const float* b_ih0 = (const float*)d_in[3];
    const float* b_hh0 = (const float*)d_in[4];
    const float* W_ih1 = (const float*)d_in[5];
    const float* W_hh1 = (const float*)d_in[6];
    const float* b_ih1 = (const float*)d_in[7];
    const float* b_hh1 = (const float*)d_in[8];
    const float* W1    = (const float*)d_in[9];
    const float* b1    = (const float*)d_in[10];
    const float* W2    = (const float*)d_in[11];
    const float* b2    = (const float*)d_in[12];
    float* out = (float*)d_out;

    float *gi, *seq, *hlast;
    cudaGetSymbolAddress((void**)&gi,    g_gi);
    cudaGetSymbolAddress((void**)&seq,   g_seq);
    cudaGetSymbolAddress((void**)&hlast, g_hlast);

    cudaFuncSetAttribute(gru_layer, cudaFuncAttributeMaxDynamicSharedMemorySize,
                         (int)GRU_SMEM);

    dim3 ggrid(MTOT / BM, G3 / BN);   // (4096, 6)

    // layer 0 input projection: gi0 = x @ W_ih0^T + b_ih0
    gemm_bias<<<ggrid, 256>>>(x, W_ih0, b_ih0, gi, MTOT, G3, II);
    // layer 0 recurrence -> full sequence
    gru_layer<<<BATCH / NB, G3, GRU_SMEM>>>(gi, W_hh0, b_hh0, seq, nullptr, 1);
    // layer 1 input projection: gi1 = seq0 @ W_ih1^T + b_ih1 (reuse gi)
    gemm_bias<<<ggrid, 256>>>(seq, W_ih1, b_ih1, gi, MTOT, G3, HH);
    // layer 1 recurrence -> last hidden only
    gru_layer<<<BATCH / NB, G3, GRU_SMEM>>>(gi, W_hh1, b_hh1, nullptr, hlast, 0);
    // head
    head_kernel<<<BATCH, 64>>>(hlast, W1, b1, W2, b2, out);
}

// round 2
// speedup vs baseline: 1.0159x; 1.0159x over previous
#include <cuda_runtime.h>
#include <cuda_bf16.h>
#include <math.h>

typedef unsigned long long ull;

// Problem constants
#define BATCH 1024
#define TT    256
#define II    153
#define HH    128
#define G3    384
#define MTOT  (BATCH*TT)   // 262144

// ---------------------------------------------------------------------------
// f32x2 packed math (Blackwell sm_10x; ptxas never emits these from C++)
// ---------------------------------------------------------------------------
__device__ __forceinline__ ull pack2(float x, float y) {
    ull r; asm("mov.b64 %0, {%1, %2};" : "=l"(r) : "f"(x), "f"(y)); return r;
}
__device__ __forceinline__ void unpack2(ull v, float& x, float& y) {
    asm("mov.b64 {%0, %1}, %2;" : "=f"(x), "=f"(y) : "l"(v));
}
__device__ __forceinline__ ull fma2(ull a, ull b, ull c) {
    ull d; asm("fma.rn.f32x2 %0, %1, %2, %3;" : "=l"(d) : "l"(a), "l"(b), "l"(c));
    return d;
}

// ---------------------------------------------------------------------------
// Scratch (device globals — no runtime allocation allowed)
// ---------------------------------------------------------------------------
__device__ float g_gi[(size_t)MTOT * G3];    // ~403 MB
__device__ float g_seq[(size_t)MTOT * HH];   // ~134 MB
__device__ float g_hlast[BATCH * HH];

// ---------------------------------------------------------------------------
// GEMM: C[M,N] = A[M,K] @ W[N,K]^T + bias[N]
// 128x64 tile, BK=16, 256 threads, 8x4 thread tile, f32x2 packed along m,
// double-buffered smem (1 barrier per k-tile).
// ---------------------------------------------------------------------------
#define BM 128
#define BN 64
#define BK 16
#define SA_LD 132   // 128 + 4 pad, keeps 16B alignment (132*4 = 528 = 33*16)
#define SB_LD 68    // 64 + 4 pad  (68*4 = 272 = 17*16)

__global__ __launch_bounds__(256)
void gemm_bias(const float* __restrict__ A, const float* __restrict__ W,
               const float* __restrict__ bias, float* __restrict__ C,
               int M, int N, int K)
{
    __shared__ float sa[2][BK * SA_LD];
    __shared__ float sb[2][BK * SB_LD];

    const int tid = threadIdx.x;
    const int tx = tid & 15;          // n dir: 16 x 4  = 64
    const int ty = tid >> 4;          // m dir: 16 x 8  = 128
    const size_t m0 = (size_t)blockIdx.x * BM;
    const int n0 = blockIdx.y * BN;

    const int arow = tid >> 1, acol = (tid & 1) * 8;   // A tile: 128 rows x 16 k
    const int brow = tid >> 2, bcol = (tid & 3) * 4;   // B tile: 64 rows x 16 k

    ull acc[4][4];
    const ull zz = pack2(0.f, 0.f);
#pragma unroll
    for (int i = 0; i < 4; i++)
#pragma unroll
        for (int j = 0; j < 4; j++) acc[i][j] = zz;

    const int KT = (K + BK - 1) / BK;
    float ar[8], br[4];

    // prologue: tile 0 -> smem[0]
#pragma unroll
    for (int i = 0; i < 8; i++) {
        int k = acol + i;
        ar[i] = (k < K) ? A[(m0 + arow) * K + k] : 0.f;
    }
#pragma unroll
    for (int i = 0; i < 4; i++) {
        int k = bcol + i;
        br[i] = (k < K) ? W[(size_t)(n0 + brow) * K + k] : 0.f;
    }
#pragma unroll
    for (int i = 0; i < 8; i++) sa[0][(acol + i) * SA_LD + arow] = ar[i];
#pragma unroll
    for (int i = 0; i < 4; i++) sb[0][(bcol + i) * SB_LD + brow] = br[i];
    __syncthreads();

    int buf = 0;
    for (int kt = 0; kt < KT; kt++) {
        const int k0n = (kt + 1) * BK;
        if (kt + 1 < KT) {
#pragma unroll
            for (int i = 0; i < 8; i++) {
                int k = k0n + acol + i;
                ar[i] = (k < K) ? A[(m0 + arow) * K + k] : 0.f;
            }
#pragma unroll
            for (int i = 0; i < 4; i++) {
                int k = k0n + bcol + i;
                br[i] = (k < K) ? W[(size_t)(n0 + brow) * K + k] : 0.f;
            }
        }

#pragma unroll
        for (int kk = 0; kk < BK; kk++) {
            const float* pa = &sa[buf][kk * SA_LD + ty * 8];
            ulonglong2 a01 = *(const ulonglong2*)pa;        // m pairs 0,1
            ulonglong2 a23 = *(const ulonglong2*)(pa + 4);  // m pairs 2,3
            float4 bv = *(const float4*)&sb[buf][kk * SB_LD + tx * 4];
            ull a2[4] = { a01.x, a01.y, a23.x, a23.y };
            ull b2[4] = { pack2(bv.x, bv.x), pack2(bv.y, bv.y),
                          pack2(bv.z, bv.z), pack2(bv.w, bv.w) };
#pragma unroll
            for (int i = 0; i < 4; i++)
#pragma unroll
                for (int j = 0; j < 4; j++)
                    acc[i][j] = fma2(a2[i], b2[j], acc[i][j]);
        }

        if (kt + 1 < KT) {
#pragma unroll
            for (int i = 0; i < 8; i++) sa[buf ^ 1][(acol + i) * SA_LD + arow] = ar[i];
#pragma unroll
            for (int i = 0; i < 4; i++) sb[buf ^ 1][(bcol + i) * SB_LD + brow] = br[i];
        }
        __syncthreads();
        buf ^= 1;
    }

    // epilogue
    float4 bs = *(const float4*)&bias[n0 + tx * 4];
    const float* bsp = (const float*)&bs;
#pragma unroll
    for (int i = 0; i < 4; i++) {
        float lo[4], hi[4];
#pragma unroll
        for (int j = 0; j < 4; j++) {
            float x, y;
            unpack2(acc[i][j], x, y);
            lo[j] = x + bsp[j];
            hi[j] = y + bsp[j];
        }
        size_t m = m0 + (size_t)ty * 8 + i * 2;
        float4 v0 = { lo[0], lo[1], lo[2], lo[3] };
        float4 v1 = { hi[0], hi[1], hi[2], hi[3] };
        *(float4*)&C[m * N + n0 + tx * 4]       = v0;
        *(float4*)&C[(m + 1) * N + n0 + tx * 4] = v1;
    }
}

// ---------------------------------------------------------------------------
// GRU recurrence. One CTA = 8 batch rows, 768 threads:
//   gid = tid % 384 (gate index), half = tid/384 -> batches [half*4, half*4+4)
// W_hh^T in smem as float4 W4[k/4][g][4]  (conflict-free vector loads)
// h in smem pair-packed: hf[pair][k][2]   (f32x2 operand loads are free)
// gates: gid in [0,128)=r, [128,256)=z, [256,384)=n (warp-uniform)
// ---------------------------------------------------------------------------
#define NB 8
#define NTH 768
#define GRU_SMEM ((49152 + 3 * 1024) * sizeof(float))   // 208896 B

__global__ __launch_bounds__(NTH)
void gru_layer(const float* __restrict__ gi,     // [B*T, 384], m = b*T + t
               const float* __restrict__ W_hh,   // [384, 128]
               const float* __restrict__ b_hh,   // [384]
               float* __restrict__ seq_out,      // [B*T, 128] (layer 0)
               float* __restrict__ hlast_out,    // [B, 128]   (layer 1)
               int write_seq)
{
    extern __shared__ float sm[];
    float* hf = sm + 49152;          // [4 pairs][128 k][2] = 1024 floats
    float* rb = hf + 1024;           // [8][128]
    float* zb = rb + 1024;           // [8][128]

    const int tid  = threadIdx.x;
    const int gid  = tid % 384;
    const int half = tid / 384;
    const int b0   = blockIdx.x * NB;
    const int j    = gid & 127;
    const int gtype = gid >> 7;

    // fill W4 (each half loads 64 of the 128 k-rows of its gate column)
    for (int k = half * 64; k < half * 64 + 64; k++)
        sm[(k >> 2) * 1536 + gid * 4 + (k & 3)] = W_hh[gid * HH + k];
    for (int i = tid; i < 1024; i += NTH) hf[i] = 0.f;

    const float bh = b_hh[gid];
    __syncthreads();

    const float* hp0 = hf + half * 512;        // pair p0 = half*2
    const float* hp1 = hp0 + 256;              // pair p0+1

    for (int t = 0; t < TT; t++) {
        // prefetch gi for this step (independent of h)
        float giv[4];
#pragma unroll
        for (int b = 0; b < 4; b++)
            giv[b] = gi[((size_t)((b0 + half * 4 + b) * TT + t)) * G3 + gid];

        ull acc0 = pack2(bh, bh);
        ull acc1 = acc0;

#pragma unroll 8
        for (int kc = 0; kc < 32; kc++) {
            float4 w4 = *(const float4*)(sm + kc * 1536 + gid * 4);
            ulonglong2 hA0 = *(const ulonglong2*)(hp0 + kc * 8);      // k0,k0+1
            ulonglong2 hB0 = *(const ulonglong2*)(hp0 + kc * 8 + 4);  // k0+2,k0+3
            ulonglong2 hA1 = *(const ulonglong2*)(hp1 + kc * 8);
            ulonglong2 hB1 = *(const ulonglong2*)(hp1 + kc * 8 + 4);
            ull w0 = pack2(w4.x, w4.x), w1 = pack2(w4.y, w4.y);
            ull w2 = pack2(w4.z, w4.z), w3 = pack2(w4.w, w4.w);
            acc0 = fma2(w0, hA0.x, acc0);
            acc1 = fma2(w0, hA1.x, acc1);
            acc0 = fma2(w1, hA0.y, acc0);
            acc1 = fma2(w1, hA1.y, acc1);
            acc0 = fma2(w2, hB0.x, acc0);
            acc1 = fma2(w2, hB1.x, acc1);
            acc0 = fma2(w3, hB0.y, acc0);
            acc1 = fma2(w3, hB1.y, acc1);
        }

        float ghv[4];
        unpack2(acc0, ghv[0], ghv[1]);
        unpack2(acc1, ghv[2], ghv[3]);

        if (gtype == 0) {
#pragma unroll
            for (int i = 0; i < 4; i++)
                rb[(half * 4 + i) * HH + j] = 1.f / (1.f + expf(-(giv[i] + ghv[i])));
        } else if (gtype == 1) {
#pragma unroll
            for (int i = 0; i < 4; i++)
                zb[(half * 4 + i) * HH + j] = 1.f / (1.f + expf(-(giv[i] + ghv[i])));
        }
        __syncthreads();

        if (gtype == 2) {
#pragma unroll
            for (int i = 0; i < 4; i++) {
                int b = half * 4 + i;
                int hidx = (half * 2 + (i >> 1)) * 256 + j * 2 + (i & 1);
                float hold = hf[hidx];
                float r = rb[b * HH + j];
                float z = zb[b * HH + j];
                float n = tanhf(giv[i] + r * ghv[i]);
                float hn = (1.f - z) * n + z * hold;
                hf[hidx] = hn;
                if (write_seq)
                    seq_out[((size_t)((b0 + b) * TT + t)) * HH + j] = hn;
            }
        }
        __syncthreads();
    }

    if (!write_seq && gtype == 2) {
#pragma unroll
        for (int i = 0; i < 4; i++) {
            int b = half * 4 + i;
            int hidx = (half * 2 + (i >> 1)) * 256 + j * 2 + (i & 1);
            hlast_out[(b0 + b) * HH + j] = hf[hidx];
        }
    }
}

// ---------------------------------------------------------------------------
// head — Linear(128,64) -> ReLU -> Linear(64,1) -> Sigmoid
// ---------------------------------------------------------------------------
__global__ __launch_bounds__(64)
void head_kernel(const float* __restrict__ hlast, const float* __restrict__ W1,
                 const float* __restrict__ b1, const float* __restrict__ W2,
                 const float* __restrict__ b2, float* __restrict__ out)
{
    __shared__ float hs[HH];
    __shared__ float partial[2];
    const int b = blockIdx.x, tid = threadIdx.x;

    hs[tid]      = hlast[b * HH + tid];
    hs[tid + 64] = hlast[b * HH + 64 + tid];
    __syncthreads();

    float acc = b1[tid];
#pragma unroll 4
    for (int k = 0; k < HH; k++)
        acc += hs[k] * W1[tid * HH + k];
    float v = fmaxf(acc, 0.f) * W2[tid];

#pragma unroll
    for (int o = 16; o > 0; o >>= 1)
        v += __shfl_down_sync(0xffffffffu, v, o);
    if ((tid & 31) == 0) partial[tid >> 5] = v;
    __syncthreads();
    if (tid == 0)
        out[b] = 1.f / (1.f + expf(-(partial[0] + partial[1] + b2[0])));
}

// ---------------------------------------------------------------------------
// Launch: proj0 -> rec0 -> proj1 (reuses g_gi) -> rec1 -> head
// ---------------------------------------------------------------------------
extern "C" void kernel_launch(void* const* d_in, const int* in_sizes, int n_in,
                              void* d_out, int out_size)
{
    (void)in_sizes; (void)n_in; (void)out_size;
    const float* x     = (const float*)d_in[0];
    const float* W_ih0 = (const float*)d_in[1];
    const float* W_hh0 = (const float*)d_in[2];
    const float* b_ih0 = (const float*)d_in[3];
    const float* b_hh0 = (const float*)d_in[4];
    const float* W_ih1 = (const float*)d_in[5];
    const float* W_hh1 = (const float*)d_in[6];
    const float* b_ih1 = (const float*)d_in[7];
    const float* b_hh1 = (const float*)d_in[8];
    const float* W1    = (const float*)d_in[9];
    const float* b1    = (const float*)d_in[10];
    const float* W2    = (const float*)d_in[11];
    const float* b2    = (const float*)d_in[12];
    float* out = (float*)d_out;

    float *gi, *seq, *hlast;
    cudaGetSymbolAddress((void**)&gi,    g_gi);
    cudaGetSymbolAddress((void**)&seq,   g_seq);
    cudaGetSymbolAddress((void**)&hlast, g_hlast);

    cudaFuncSetAttribute(gru_layer, cudaFuncAttributeMaxDynamicSharedMemorySize,
                         (int)GRU_SMEM);

    dim3 ggrid(MTOT / BM, G3 / BN);   // (2048, 6)

    gemm_bias<<<ggrid, 256>>>(x, W_ih0, b_ih0, gi, MTOT, G3, II);
    gru_layer<<<BATCH / NB, NTH, GRU_SMEM>>>(gi, W_hh0, b_hh0, seq, nullptr, 1);
    gemm_bias<<<ggrid, 256>>>(seq, W_ih1, b_ih1, gi, MTOT, G3, HH);
    gru_layer<<<BATCH / NB, NTH, GRU_SMEM>>>(gi, W_hh1, b_hh1, nullptr, hlast, 0);
    head_kernel<<<BATCH, 64>>>(hlast, W1, b1, W2, b2, out);
}

// round 3
// speedup vs baseline: 1.3409x; 1.3199x over previous
#include <cuda_runtime.h>
#include <cuda_bf16.h>
#include <math.h>

typedef unsigned long long ull;
typedef unsigned int uint;

// Problem constants
#define BATCH 1024
#define TT    256
#define II    153
#define HH    128
#define G3    384
#define MTOT  (BATCH*TT)   // 262144

// ---------------------------------------------------------------------------
// Scratch (device globals — no runtime allocation allowed)
// ---------------------------------------------------------------------------
__device__ float g_gi[(size_t)MTOT * G3];    // ~403 MB
__device__ float g_seq[(size_t)MTOT * HH];   // ~134 MB
__device__ float g_hlast[BATCH * HH];

// ---------------------------------------------------------------------------
// f32x2 packed math (kept for the GRU kernel)
// ---------------------------------------------------------------------------
__device__ __forceinline__ ull pack2(float x, float y) {
    ull r; asm("mov.b64 %0, {%1, %2};" : "=l"(r) : "f"(x), "f"(y)); return r;
}
__device__ __forceinline__ void unpack2(ull v, float& x, float& y) {
    asm("mov.b64 {%0, %1}, %2;" : "=f"(x), "=f"(y) : "l"(v));
}
__device__ __forceinline__ ull fma2(ull a, ull b, ull c) {
    ull d; asm("fma.rn.f32x2 %0, %1, %2, %3;" : "=l"(d) : "l"(a), "l"(b), "l"(c));
    return d;
}

// ---------------------------------------------------------------------------
// Tensor-core helpers (mma.sync bf16 + ldmatrix)
// ---------------------------------------------------------------------------
__device__ __forceinline__ void split_bf16(float a, unsigned short& h, unsigned short& l) {
    __nv_bfloat16 bh = __float2bfloat16(a);              // round-to-nearest
    float r = a - __bfloat162float(bh);
    __nv_bfloat16 bl = __float2bfloat16(r);
    h = __bfloat16_as_ushort(bh);
    l = __bfloat16_as_ushort(bl);
}
__device__ __forceinline__ void ldsm_x4(uint& r0, uint& r1, uint& r2, uint& r3, uint addr) {
    asm volatile("ldmatrix.sync.aligned.m8n8.x4.shared.b16 {%0,%1,%2,%3}, [%4];"
        : "=r"(r0), "=r"(r1), "=r"(r2), "=r"(r3) : "r"(addr));
}
__device__ __forceinline__ void mma_bf16(float* d, const uint* a, const uint* b) {
    asm volatile("mma.sync.aligned.m16n8k16.row.col.f32.bf16.bf16.f32 "
        "{%0,%1,%2,%3}, {%4,%5,%6,%7}, {%8,%9}, {%0,%1,%2,%3};"
        : "+f"(d[0]), "+f"(d[1]), "+f"(d[2]), "+f"(d[3])
        : "r"(a[0]), "r"(a[1]), "r"(a[2]), "r"(a[3]), "r"(b[0]), "r"(b[1]));
}

// ---------------------------------------------------------------------------
// Tensor-core GEMM with bf16 3-term split (fp32-accurate to ~1e-5):
//   C[M,384] = A[M,K] @ W[384,K]^T + bias
//   C ≈ Ah·Wh + Ah·Wl + Al·Wh
// CTA tile 128x128, 8 warps (2m x 4n), warp tile 64x32, k-tile 16.
// smem rows padded to 40 halfs -> ldmatrix conflict-free (banks 20r mod 32).
// ---------------------------------------------------------------------------
#define TLD 40   // smem row stride in halfs: 16 hi | 16 lo | 8 pad

__global__ __launch_bounds__(256, 2)
void gemm_tc(const float* __restrict__ A, const float* __restrict__ W,
             const float* __restrict__ bias, float* __restrict__ C, int K)
{
    __shared__ __align__(16) unsigned short sa[2][128 * TLD];
    __shared__ __align__(16) unsigned short sb[2][128 * TLD];

    const int tid  = threadIdx.x;
    const int warp = tid >> 5;
    const int lane = tid & 31;
    const size_t m0 = (size_t)blockIdx.x * 128;
    const int n0 = blockIdx.y * 128;
    const int wm = (warp >> 2) * 64;    // warp m-offset (0 or 64)
    const int wn = (warp & 3) * 32;     // warp n-offset (0,32,64,96)

    // global->reg load mapping: 4 iters, each thread 2 consecutive k of one row
    const int lrow = tid >> 3;          // 0..31
    const int lcol = (tid & 7) * 2;     // 0,2,..,14

    float acc[4][4][4];
#pragma unroll
    for (int i = 0; i < 4; i++)
#pragma unroll
        for (int j = 0; j < 4; j++)
#pragma unroll
            for (int v = 0; v < 4; v++) acc[i][j][v] = 0.f;

    const int KT = (K + 15) / 16;
    float ar[8], br[8];

    // ---- prologue: k-tile 0 -> regs -> smem[0]
#pragma unroll
    for (int it = 0; it < 4; it++) {
        int row = it * 32 + lrow;
        int k = lcol;
        ar[it*2]   = (k     < K) ? A[(m0 + row) * K + k]     : 0.f;
        ar[it*2+1] = (k + 1 < K) ? A[(m0 + row) * K + k + 1] : 0.f;
        br[it*2]   = (k     < K) ? W[(size_t)(n0 + row) * K + k]     : 0.f;
        br[it*2+1] = (k + 1 < K) ? W[(size_t)(n0 + row) * K + k + 1] : 0.f;
    }
#pragma unroll
    for (int it = 0; it < 4; it++) {
        int row = it * 32 + lrow;
        unsigned short h0, l0, h1, l1;
        split_bf16(ar[it*2], h0, l0); split_bf16(ar[it*2+1], h1, l1);
        *(uint*)&sa[0][row * TLD + lcol]      = (uint)h0 | ((uint)h1 << 16);
        *(uint*)&sa[0][row * TLD + 16 + lcol] = (uint)l0 | ((uint)l1 << 16);
        split_bf16(br[it*2], h0, l0); split_bf16(br[it*2+1], h1, l1);
        *(uint*)&sb[0][row * TLD + lcol]      = (uint)h0 | ((uint)h1 << 16);
        *(uint*)&sb[0][row * TLD + 16 + lcol] = (uint)l0 | ((uint)l1 << 16);
    }
    __syncthreads();

    int buf = 0;
    for (int kt = 0; kt < KT; kt++) {
        // prefetch next tile
        if (kt + 1 < KT) {
            int kb = (kt + 1) * 16;
#pragma unroll
            for (int it = 0; it < 4; it++) {
                int row = it * 32 + lrow;
                int k = kb + lcol;
                ar[it*2]   = (k     < K) ? A[(m0 + row) * K + k]     : 0.f;
                ar[it*2+1] = (k + 1 < K) ? A[(m0 + row) * K + k + 1] : 0.f;
                br[it*2]   = (k     < K) ? W[(size_t)(n0 + row) * K + k]     : 0.f;
                br[it*2+1] = (k + 1 < K) ? W[(size_t)(n0 + row) * K + k + 1] : 0.f;
            }
        }

        uint sa_base = (uint)__cvta_generic_to_shared(&sa[buf][0]);
        uint sb_base = (uint)__cvta_generic_to_shared(&sb[buf][0]);

        // B fragments for this warp's 32 n-columns (hi and lo)
        uint bh[8], bl[8];
#pragma unroll
        for (int g = 0; g < 2; g++) {
            int nrow = wn + g * 16 + ((lane & 16) >> 1) + (lane & 7);
            int kcol = ((lane >> 3) & 1) * 8;
            ldsm_x4(bh[g*4+0], bh[g*4+1], bh[g*4+2], bh[g*4+3],
                    sb_base + (uint)(nrow * TLD + kcol) * 2u);
            ldsm_x4(bl[g*4+0], bl[g*4+1], bl[g*4+2], bl[g*4+3],
                    sb_base + (uint)(nrow * TLD + 16 + kcol) * 2u);
        }

#pragma unroll
        for (int mi = 0; mi < 4; mi++) {
            int arow = wm + mi * 16 + (lane & 15);
            int acol = ((lane >> 4) & 1) * 8;
            uint ah[4], al[4];
            ldsm_x4(ah[0], ah[1], ah[2], ah[3],
                    sa_base + (uint)(arow * TLD + acol) * 2u);
            ldsm_x4(al[0], al[1], al[2], al[3],
                    sa_base + (uint)(arow * TLD + 16 + acol) * 2u);
#pragma unroll
            for (int ni = 0; ni < 4; ni++) {
                mma_bf16(acc[mi][ni], ah, &bh[ni*2]);   // Ah*Wh
                mma_bf16(acc[mi][ni], ah, &bl[ni*2]);   // Ah*Wl
                mma_bf16(acc[mi][ni], al, &bh[ni*2]);   // Al*Wh
            }
        }

        if (kt + 1 < KT) {
            int nb = buf ^ 1;
#pragma unroll
            for (int it = 0; it < 4; it++) {
                int row = it * 32 + lrow;
                unsigned short h0, l0, h1, l1;
                split_bf16(ar[it*2], h0, l0); split_bf16(ar[it*2+1], h1, l1);
                *(uint*)&sa[nb][row * TLD + lcol]      = (uint)h0 | ((uint)h1 << 16);
                *(uint*)&sa[nb][row * TLD + 16 + lcol] = (uint)l0 | ((uint)l1 << 16);
                split_bf16(br[it*2], h0, l0); split_bf16(br[it*2+1], h1, l1);
                *(uint*)&sb[nb][row * TLD + lcol]      = (uint)h0 | ((uint)h1 << 16);
                *(uint*)&sb[nb][row * TLD + 16 + lcol] = (uint)l0 | ((uint)l1 << 16);
            }
        }
        __syncthreads();
        buf ^= 1;
    }

    // ---- epilogue: D frag layout m16n8 -> rows lane>>2 (+8), cols (lane&3)*2
    const int r = lane >> 2;
    const int c2 = (lane & 3) * 2;
#pragma unroll
    for (int mi = 0; mi < 4; mi++) {
#pragma unroll
        for (int ni = 0; ni < 4; ni++) {
            int n = n0 + wn + ni * 8 + c2;
            float b0 = bias[n], b1 = bias[n + 1];
            size_t m = m0 + wm + mi * 16 + r;
            float2 v0 = { acc[mi][ni][0] + b0, acc[mi][ni][1] + b1 };
            float2 v1 = { acc[mi][ni][2] + b0, acc[mi][ni][3] + b1 };
            *(float2*)&C[m * G3 + n]       = v0;
            *(float2*)&C[(m + 8) * G3 + n] = v1;
        }
    }
}

// ---------------------------------------------------------------------------
// GRU recurrence (unchanged from R1 — passes; optimize next round).
// One CTA = 8 batch rows, 768 threads.
// ---------------------------------------------------------------------------
#define NB 8
#define NTH 768
#define GRU_SMEM ((49152 + 3 * 1024) * sizeof(float))   // 208896 B

__global__ __launch_bounds__(NTH)
void gru_layer(const float* __restrict__ gi,     // [B*T, 384], m = b*T + t
               const float* __restrict__ W_hh,   // [384, 128]
               const float* __restrict__ b_hh,   // [384]
               float* __restrict__ seq_out,      // [B*T, 128] (layer 0)
               float* __restrict__ hlast_out,    // [B, 128]   (layer 1)
               int write_seq)
{
    extern __shared__ float sm[];
    float* hf = sm + 49152;          // [4 pairs][128 k][2] = 1024 floats
    float* rb = hf + 1024;           // [8][128]
    float* zb = rb + 1024;           // [8][128]

    const int tid  = threadIdx.x;
    const int gid  = tid % 384;
    const int half = tid / 384;
    const int b0   = blockIdx.x * NB;
    const int j    = gid & 127;
    const int gtype = gid >> 7;

    for (int k = half * 64; k < half * 64 + 64; k++)
        sm[(k >> 2) * 1536 + gid * 4 + (k & 3)] = W_hh[gid * HH + k];
    for (int i = tid; i < 1024; i += NTH) hf[i] = 0.f;

    const float bh = b_hh[gid];
    __syncthreads();

    const float* hp0 = hf + half * 512;
    const float* hp1 = hp0 + 256;

    for (int t = 0; t < TT; t++) {
        float giv[4];
#pragma unroll
        for (int b = 0; b < 4; b++)
            giv[b] = gi[((size_t)((b0 + half * 4 + b) * TT + t)) * G3 + gid];

        ull acc0 = pack2(bh, bh);
        ull acc1 = acc0;

#pragma unroll 8
        for (int kc = 0; kc < 32; kc++) {
            float4 w4 = *(const float4*)(sm + kc * 1536 + gid * 4);
            ulonglong2 hA0 = *(const ulonglong2*)(hp0 + kc * 8);
            ulonglong2 hB0 = *(const ulonglong2*)(hp0 + kc * 8 + 4);
            ulonglong2 hA1 = *(const ulonglong2*)(hp1 + kc * 8);
            ulonglong2 hB1 = *(const ulonglong2*)(hp1 + kc * 8 + 4);
            ull w0 = pack2(w4.x, w4.x), w1 = pack2(w4.y, w4.y);
            ull w2 = pack2(w4.z, w4.z), w3 = pack2(w4.w, w4.w);
            acc0 = fma2(w0, hA0.x, acc0);
            acc1 = fma2(w0, hA1.x, acc1);
            acc0 = fma2(w1, hA0.y, acc0);
            acc1 = fma2(w1, hA1.y, acc1);
            acc0 = fma2(w2, hB0.x, acc0);
            acc1 = fma2(w2, hB1.x, acc1);
            acc0 = fma2(w3, hB0.y, acc0);
            acc1 = fma2(w3, hB1.y, acc1);
        }

        float ghv[4];
        unpack2(acc0, ghv[0], ghv[1]);
        unpack2(acc1, ghv[2], ghv[3]);

        if (gtype == 0) {
#pragma unroll
            for (int i = 0; i < 4; i++)
                rb[(half * 4 + i) * HH + j] = 1.f / (1.f + expf(-(giv[i] + ghv[i])));
        } else if (gtype == 1) {
#pragma unroll
            for (int i = 0; i < 4; i++)
                zb[(half * 4 + i) * HH + j] = 1.f / (1.f + expf(-(giv[i] + ghv[i])));
        }
        __syncthreads();

        if (gtype == 2) {
#pragma unroll
            for (int i = 0; i < 4; i++) {
                int b = half * 4 + i;
                int hidx = (half * 2 + (i >> 1)) * 256 + j * 2 + (i & 1);
                float hold = hf[hidx];
                float r = rb[b * HH + j];
                float z = zb[b * HH + j];
                float n = tanhf(giv[i] + r * ghv[i]);
                float hn = (1.f - z) * n + z * hold;
                hf[hidx] = hn;
                if (write_seq)
                    seq_out[((size_t)((b0 + b) * TT + t)) * HH + j] = hn;
            }
        }
        __syncthreads();
    }

    if (!write_seq && gtype == 2) {
#pragma unroll
        for (int i = 0; i < 4; i++) {
            int b = half * 4 + i;
            int hidx = (half * 2 + (i >> 1)) * 256 + j * 2 + (i & 1);
            hlast_out[(b0 + b) * HH + j] = hf[hidx];
        }
    }
}

// ---------------------------------------------------------------------------
// head — Linear(128,64) -> ReLU -> Linear(64,1) -> Sigmoid
// ---------------------------------------------------------------------------
__global__ __launch_bounds__(64)
void head_kernel(const float* __restrict__ hlast, const float* __restrict__ W1,
                 const float* __restrict__ b1, const float* __restrict__ W2,
                 const float* __restrict__ b2, float* __restrict__ out)
{
    __shared__ float hs[HH];
    __shared__ float partial[2];
    const int b = blockIdx.x, tid = threadIdx.x;

    hs[tid]      = hlast[b * HH + tid];
    hs[tid + 64] = hlast[b * HH + 64 + tid];
    __syncthreads();

    float acc = b1[tid];
#pragma unroll 4
    for (int k = 0; k < HH; k++)
        acc += hs[k] * W1[tid * HH + k];
    float v = fmaxf(acc, 0.f) * W2[tid];

#pragma unroll
    for (int o = 16; o > 0; o >>= 1)
        v += __shfl_down_sync(0xffffffffu, v, o);
    if ((tid & 31) == 0) partial[tid >> 5] = v;
    __syncthreads();
    if (tid == 0)
        out[b] = 1.f / (1.f + expf(-(partial[0] + partial[1] + b2[0])));
}

// ---------------------------------------------------------------------------
// Launch: proj0 -> rec0 -> proj1 (reuses g_gi) -> rec1 -> head
// ---------------------------------------------------------------------------
extern "C" void kernel_launch(void* const* d_in, const int* in_sizes, int n_in,
                              void* d_out, int out_size)
{
    (void)in_sizes; (void)n_in; (void)out_size;
    const float* x     = (const float*)d_in[0];
    const float* W_ih0 = (const float*)d_in[1];
    const float* W_hh0 = (const float*)d_in[2];
    const float* b_ih0 = (const float*)d_in[3];
    const float* b_hh0 = (const float*)d_in[4];
    const float* W_ih1 = (const float*)d_in[5];
    const float* W_hh1 = (const float*)d_in[6];
    const float* b_ih1 = (const float*)d_in[7];
    const float* b_hh1 = (const float*)d_in[8];
    const float* W1    = (const float*)d_in[9];
    const float* b1    = (const float*)d_in[10];
    const float* W2    = (const float*)d_in[11];
    const float* b2    = (const float*)d_in[12];
    float* out = (float*)d_out;

    float *gi, *seq, *hlast;
    cudaGetSymbolAddress((void**)&gi,    g_gi);
    cudaGetSymbolAddress((void**)&seq,   g_seq);
    cudaGetSymbolAddress((void**)&hlast, g_hlast);

    cudaFuncSetAttribute(gru_layer, cudaFuncAttributeMaxDynamicSharedMemorySize,
                         (int)GRU_SMEM);

    dim3 tgrid(MTOT / 128, G3 / 128);   // (2048, 3)

    gemm_tc<<<tgrid, 256>>>(x, W_ih0, b_ih0, gi, II);
    gru_layer<<<BATCH / NB, NTH, GRU_SMEM>>>(gi, W_hh0, b_hh0, seq, nullptr, 1);
    gemm_tc<<<tgrid, 256>>>(seq, W_ih1, b_ih1, gi, HH);
    gru_layer<<<BATCH / NB, NTH, GRU_SMEM>>>(gi, W_hh1, b_hh1, nullptr, hlast, 0);
    head_kernel<<<BATCH, 64>>>(hlast, W1, b1, W2, b2, out);
}

// round 4
// speedup vs baseline: 1.5249x; 1.1372x over previous
#include <cuda_runtime.h>
#include <cuda_bf16.h>
#include <math.h>

typedef unsigned long long ull;
typedef unsigned int uint;

// Problem constants
#define BATCH 1024
#define TT    256
#define II    153
#define HH    128
#define G3    384
#define MTOT  (BATCH*TT)   // 262144

// ---------------------------------------------------------------------------
// Scratch (device globals — no runtime allocation allowed)
// ---------------------------------------------------------------------------
__device__ float g_gi[(size_t)MTOT * G3];    // ~403 MB
__device__ float g_seq[(size_t)MTOT * HH];   // ~134 MB
__device__ float g_hlast[BATCH * HH];

// ---------------------------------------------------------------------------
// f32x2 packed math
// ---------------------------------------------------------------------------
__device__ __forceinline__ ull pack2(float x, float y) {
    ull r; asm("mov.b64 %0, {%1, %2};" : "=l"(r) : "f"(x), "f"(y)); return r;
}
__device__ __forceinline__ void unpack2(ull v, float& x, float& y) {
    asm("mov.b64 {%0, %1}, %2;" : "=f"(x), "=f"(y) : "l"(v));
}
__device__ __forceinline__ ull fma2(ull a, ull b, ull c) {
    ull d; asm("fma.rn.f32x2 %0, %1, %2, %3;" : "=l"(d) : "l"(a), "l"(b), "l"(c));
    return d;
}

// ---------------------------------------------------------------------------
// Tensor-core helpers (mma.sync bf16 + ldmatrix)
// ---------------------------------------------------------------------------
__device__ __forceinline__ void split_bf16(float a, unsigned short& h, unsigned short& l) {
    __nv_bfloat16 bh = __float2bfloat16(a);
    float r = a - __bfloat162float(bh);
    __nv_bfloat16 bl = __float2bfloat16(r);
    h = __bfloat16_as_ushort(bh);
    l = __bfloat16_as_ushort(bl);
}
__device__ __forceinline__ void ldsm_x4(uint& r0, uint& r1, uint& r2, uint& r3, uint addr) {
    asm volatile("ldmatrix.sync.aligned.m8n8.x4.shared.b16 {%0,%1,%2,%3}, [%4];"
        : "=r"(r0), "=r"(r1), "=r"(r2), "=r"(r3) : "r"(addr));
}
__device__ __forceinline__ void mma_bf16(float* d, const uint* a, const uint* b) {
    asm volatile("mma.sync.aligned.m16n8k16.row.col.f32.bf16.bf16.f32 "
        "{%0,%1,%2,%3}, {%4,%5,%6,%7}, {%8,%9}, {%0,%1,%2,%3};"
        : "+f"(d[0]), "+f"(d[1]), "+f"(d[2]), "+f"(d[3])
        : "r"(a[0]), "r"(a[1]), "r"(a[2]), "r"(a[3]), "r"(b[0]), "r"(b[1]));
}

// ---------------------------------------------------------------------------
// Tensor-core GEMM with bf16 3-term split (unchanged from R2 — proven)
// ---------------------------------------------------------------------------
#define TLD 40

__global__ __launch_bounds__(256, 2)
void gemm_tc(const float* __restrict__ A, const float* __restrict__ W,
             const float* __restrict__ bias, float* __restrict__ C, int K)
{
    __shared__ __align__(16) unsigned short sa[2][128 * TLD];
    __shared__ __align__(16) unsigned short sb[2][128 * TLD];

    const int tid  = threadIdx.x;
    const int warp = tid >> 5;
    const int lane = tid & 31;
    const size_t m0 = (size_t)blockIdx.x * 128;
    const int n0 = blockIdx.y * 128;
    const int wm = (warp >> 2) * 64;
    const int wn = (warp & 3) * 32;

    const int lrow = tid >> 3;
    const int lcol = (tid & 7) * 2;

    float acc[4][4][4];
#pragma unroll
    for (int i = 0; i < 4; i++)
#pragma unroll
        for (int j = 0; j < 4; j++)
#pragma unroll
            for (int v = 0; v < 4; v++) acc[i][j][v] = 0.f;

    const int KT = (K + 15) / 16;
    float ar[8], br[8];

#pragma unroll
    for (int it = 0; it < 4; it++) {
        int row = it * 32 + lrow;
        int k = lcol;
        ar[it*2]   = (k     < K) ? A[(m0 + row) * K + k]     : 0.f;
        ar[it*2+1] = (k + 1 < K) ? A[(m0 + row) * K + k + 1] : 0.f;
        br[it*2]   = (k     < K) ? W[(size_t)(n0 + row) * K + k]     : 0.f;
        br[it*2+1] = (k + 1 < K) ? W[(size_t)(n0 + row) * K + k + 1] : 0.f;
    }
#pragma unroll
    for (int it = 0; it < 4; it++) {
        int row = it * 32 + lrow;
        unsigned short h0, l0, h1, l1;
        split_bf16(ar[it*2], h0, l0); split_bf16(ar[it*2+1], h1, l1);
        *(uint*)&sa[0][row * TLD + lcol]      = (uint)h0 | ((uint)h1 << 16);
        *(uint*)&sa[0][row * TLD + 16 + lcol] = (uint)l0 | ((uint)l1 << 16);
        split_bf16(br[it*2], h0, l0); split_bf16(br[it*2+1], h1, l1);
        *(uint*)&sb[0][row * TLD + lcol]      = (uint)h0 | ((uint)h1 << 16);
        *(uint*)&sb[0][row * TLD + 16 + lcol] = (uint)l0 | ((uint)l1 << 16);
    }
    __syncthreads();

    int buf = 0;
    for (int kt = 0; kt < KT; kt++) {
        if (kt + 1 < KT) {
            int kb = (kt + 1) * 16;
#pragma unroll
            for (int it = 0; it < 4; it++) {
                int row = it * 32 + lrow;
                int k = kb + lcol;
                ar[it*2]   = (k     < K) ? A[(m0 + row) * K + k]     : 0.f;
                ar[it*2+1] = (k + 1 < K) ? A[(m0 + row) * K + k + 1] : 0.f;
                br[it*2]   = (k     < K) ? W[(size_t)(n0 + row) * K + k]     : 0.f;
                br[it*2+1] = (k + 1 < K) ? W[(size_t)(n0 + row) * K + k + 1] : 0.f;
            }
        }

        uint sa_base = (uint)__cvta_generic_to_shared(&sa[buf][0]);
        uint sb_base = (uint)__cvta_generic_to_shared(&sb[buf][0]);

        uint bhf[8], blf[8];
#pragma unroll
        for (int g = 0; g < 2; g++) {
            int nrow = wn + g * 16 + ((lane & 16) >> 1) + (lane & 7);
            int kcol = ((lane >> 3) & 1) * 8;
            ldsm_x4(bhf[g*4+0], bhf[g*4+1], bhf[g*4+2], bhf[g*4+3],
                    sb_base + (uint)(nrow * TLD + kcol) * 2u);
            ldsm_x4(blf[g*4+0], blf[g*4+1], blf[g*4+2], blf[g*4+3],
                    sb_base + (uint)(nrow * TLD + 16 + kcol) * 2u);
        }

#pragma unroll
        for (int mi = 0; mi < 4; mi++) {
            int arow = wm + mi * 16 + (lane & 15);
            int acol = ((lane >> 4) & 1) * 8;
            uint ah[4], al[4];
            ldsm_x4(ah[0], ah[1], ah[2], ah[3],
                    sa_base + (uint)(arow * TLD + acol) * 2u);
            ldsm_x4(al[0], al[1], al[2], al[3],
                    sa_base + (uint)(arow * TLD + 16 + acol) * 2u);
#pragma unroll
            for (int ni = 0; ni < 4; ni++) {
                mma_bf16(acc[mi][ni], ah, &bhf[ni*2]);
                mma_bf16(acc[mi][ni], ah, &blf[ni*2]);
                mma_bf16(acc[mi][ni], al, &bhf[ni*2]);
            }
        }

        if (kt + 1 < KT) {
            int nb = buf ^ 1;
#pragma unroll
            for (int it = 0; it < 4; it++) {
                int row = it * 32 + lrow;
                unsigned short h0, l0, h1, l1;
                split_bf16(ar[it*2], h0, l0); split_bf16(ar[it*2+1], h1, l1);
                *(uint*)&sa[nb][row * TLD + lcol]      = (uint)h0 | ((uint)h1 << 16);
                *(uint*)&sa[nb][row * TLD + 16 + lcol] = (uint)l0 | ((uint)l1 << 16);
                split_bf16(br[it*2], h0, l0); split_bf16(br[it*2+1], h1, l1);
                *(uint*)&sb[nb][row * TLD + lcol]      = (uint)h0 | ((uint)h1 << 16);
                *(uint*)&sb[nb][row * TLD + 16 + lcol] = (uint)l0 | ((uint)l1 << 16);
            }
        }
        __syncthreads();
        buf ^= 1;
    }

    const int r = lane >> 2;
    const int c2 = (lane & 3) * 2;
#pragma unroll
    for (int mi = 0; mi < 4; mi++) {
#pragma unroll
        for (int ni = 0; ni < 4; ni++) {
            int n = n0 + wn + ni * 8 + c2;
            float b0 = bias[n], b1 = bias[n + 1];
            size_t m = m0 + wm + mi * 16 + r;
            float2 v0 = { acc[mi][ni][0] + b0, acc[mi][ni][1] + b1 };
            float2 v1 = { acc[mi][ni][2] + b0, acc[mi][ni][3] + b1 };
            *(float2*)&C[m * G3 + n]       = v0;
            *(float2*)&C[(m + 8) * G3 + n] = v1;
        }
    }
}

// ---------------------------------------------------------------------------
// GRU recurrence — W_hh in REGISTERS (128 floats/thread pre-packed as 64
// f32x2 pairs along k). 384 threads, thread = gate, 8 batches per thread.
// h in smem [b][k] rows; reads are 16B broadcasts, writes conflict-free.
// acc[b] accumulates (even-k, odd-k) partials in one f32x2; summed at end.
// ---------------------------------------------------------------------------
#define NB 8
#define NTH 384

__global__ __launch_bounds__(NTH)
void gru_layer(const float* __restrict__ gi,     // [B*T, 384], m = b*T + t
               const float* __restrict__ W_hh,   // [384, 128]
               const float* __restrict__ b_hh,   // [384]
               float* __restrict__ seq_out,      // [B*T, 128] (layer 0)
               float* __restrict__ hlast_out,    // [B, 128]   (layer 1)
               int write_seq)
{
    __shared__ float hs[NB][HH];
    __shared__ float rb[NB][HH];
    __shared__ float zb[NB][HH];

    const int gid = threadIdx.x;      // 0..383 gate index
    const int b0  = blockIdx.x * NB;
    const int j   = gid & 127;
    const int gtype = gid >> 7;       // 0=r, 1=z, 2=n

    // W row gid -> registers, packed as (w[2i], w[2i+1]) pairs.
    ull Wp[64];
#pragma unroll
    for (int i = 0; i < 64; i++) {
        float2 w = *(const float2*)&W_hh[(size_t)gid * HH + 2 * i];
        Wp[i] = pack2(w.x, w.y);
    }

    for (int i = gid; i < NB * HH; i += NTH) (&hs[0][0])[i] = 0.f;
    const float bh = b_hh[gid];
    __syncthreads();

    for (int t = 0; t < TT; t++) {
        // prefetch gi (independent of h -> hidden behind k-loop)
        float giv[NB];
#pragma unroll
        for (int b = 0; b < NB; b++)
            giv[b] = gi[((size_t)((b0 + b) * TT + t)) * G3 + gid];

        ull acc[NB];
        const ull zz = pack2(0.f, 0.f);
#pragma unroll
        for (int b = 0; b < NB; b++) acc[b] = zz;

#pragma unroll
        for (int c = 0; c < 32; c++) {            // 4 ks per chunk
#pragma unroll
            for (int b = 0; b < NB; b++) {
                ulonglong2 hv = *(const ulonglong2*)&hs[b][4 * c];
                acc[b] = fma2(Wp[2 * c],     hv.x, acc[b]);
                acc[b] = fma2(Wp[2 * c + 1], hv.y, acc[b]);
            }
        }

        float gh[NB];
#pragma unroll
        for (int b = 0; b < NB; b++) {
            float x, y; unpack2(acc[b], x, y);
            gh[b] = x + y + bh;
        }

        if (gtype == 0) {
#pragma unroll
            for (int b = 0; b < NB; b++)
                rb[b][j] = 1.f / (1.f + expf(-(giv[b] + gh[b])));
        } else if (gtype == 1) {
#pragma unroll
            for (int b = 0; b < NB; b++)
                zb[b][j] = 1.f / (1.f + expf(-(giv[b] + gh[b])));
        }
        __syncthreads();

        if (gtype == 2) {
#pragma unroll
            for (int b = 0; b < NB; b++) {
                float r = rb[b][j];
                float z = zb[b][j];
                float n = tanhf(giv[b] + r * gh[b]);
                float hn = (1.f - z) * n + z * hs[b][j];
                hs[b][j] = hn;
                if (write_seq)
                    seq_out[((size_t)((b0 + b) * TT + t)) * HH + j] = hn;
            }
        }
        __syncthreads();
    }

    if (!write_seq && gtype == 2) {
#pragma unroll
        for (int b = 0; b < NB; b++)
            hlast_out[(b0 + b) * HH + j] = hs[b][j];
    }
}

// ---------------------------------------------------------------------------
// head — Linear(128,64) -> ReLU -> Linear(64,1) -> Sigmoid
// ---------------------------------------------------------------------------
__global__ __launch_bounds__(64)
void head_kernel(const float* __restrict__ hlast, const float* __restrict__ W1,
                 const float* __restrict__ b1, const float* __restrict__ W2,
                 const float* __restrict__ b2, float* __restrict__ out)
{
    __shared__ float hsm[HH];
    __shared__ float partial[2];
    const int b = blockIdx.x, tid = threadIdx.x;

    hsm[tid]      = hlast[b * HH + tid];
    hsm[tid + 64] = hlast[b * HH + 64 + tid];
    __syncthreads();

    float acc = b1[tid];
#pragma unroll 4
    for (int k = 0; k < HH; k++)
        acc += hsm[k] * W1[tid * HH + k];
    float v = fmaxf(acc, 0.f) * W2[tid];

#pragma unroll
    for (int o = 16; o > 0; o >>= 1)
        v += __shfl_down_sync(0xffffffffu, v, o);
    if ((tid & 31) == 0) partial[tid >> 5] = v;
    __syncthreads();
    if (tid == 0)
        out[b] = 1.f / (1.f + expf(-(partial[0] + partial[1] + b2[0])));
}

// ---------------------------------------------------------------------------
// Launch: proj0 -> rec0 -> proj1 (reuses g_gi) -> rec1 -> head
// ---------------------------------------------------------------------------
extern "C" void kernel_launch(void* const* d_in, const int* in_sizes, int n_in,
                              void* d_out, int out_size)
{
    (void)in_sizes; (void)n_in; (void)out_size;
    const float* x     = (const float*)d_in[0];
    const float* W_ih0 = (const float*)d_in[1];
    const float* W_hh0 = (const float*)d_in[2];
    const float* b_ih0 = (const float*)d_in[3];
    const float* b_hh0 = (const float*)d_in[4];
    const float* W_ih1 = (const float*)d_in[5];
    const float* W_hh1 = (const float*)d_in[6];
    const float* b_ih1 = (const float*)d_in[7];
    const float* b_hh1 = (const float*)d_in[8];
    const float* W1    = (const float*)d_in[9];
    const float* b1    = (const float*)d_in[10];
    const float* W2    = (const float*)d_in[11];
    const float* b2    = (const float*)d_in[12];
    float* out = (float*)d_out;

    float *gi, *seq, *hlast;
    cudaGetSymbolAddress((void**)&gi,    g_gi);
    cudaGetSymbolAddress((void**)&seq,   g_seq);
    cudaGetSymbolAddress((void**)&hlast, g_hlast);

    dim3 tgrid(MTOT / 128, G3 / 128);   // (2048, 3)

    gemm_tc<<<tgrid, 256>>>(x, W_ih0, b_ih0, gi, II);
    gru_layer<<<BATCH / NB, NTH>>>(gi, W_hh0, b_hh0, seq, nullptr, 1);
    gemm_tc<<<tgrid, 256>>>(seq, W_ih1, b_ih1, gi, HH);
    gru_layer<<<BATCH / NB, NTH>>>(gi, W_hh1, b_hh1, nullptr, hlast, 0);
    head_kernel<<<BATCH, 64>>>(hlast, W1, b1, W2, b2, out);
}